// round 3
// baseline (speedup 1.0000x reference)
#include <cuda_runtime.h>
#include <cuda_bf16.h>

#define BB 8
#define NN 2048
#define BIGF 1e30f
#define GRID 128
#define TB 256
#define RTILE 256

// Scratch (allocation-free rule). Points stored transformed: (x+y, x-y, z, 0)
// g_valid[0] = clean (points+target), g_valid[1] = predp (points+pred)
__device__ float4       g_valid[2][BB][NN];
__device__ unsigned int g_minbits[2][BB][NN];
__device__ int          g_cnt[BB];          // zero at load; reset by block0 each call
__device__ float        g_l1part[GRID];
__device__ unsigned int g_bar_cnt;          // sense-reversal barrier (self-resetting)
__device__ volatile unsigned int g_bar_gen; // monotonic across calls
__device__ volatile unsigned int g_fin;     // final arrive counter; reset each call

__device__ __forceinline__ void grid_barrier() {
    __threadfence();
    __syncthreads();
    if (threadIdx.x == 0) {
        unsigned gen = g_bar_gen;           // read before arriving: flip impossible yet
        unsigned a = atomicAdd(&g_bar_cnt, 1u);
        if (a == GRID - 1) {
            g_bar_cnt = 0;
            __threadfence();
            g_bar_gen = gen + 1;
        } else {
            while (g_bar_gen == gen) __nanosleep(32);
        }
    }
    __syncthreads();
    __threadfence();
}

__global__ void __launch_bounds__(TB, 2)
fused_kernel(const float* __restrict__ pred,
             const float* __restrict__ target,
             const int*   __restrict__ mask,
             const float* __restrict__ points,
             float* __restrict__ out) {
    int bid = blockIdx.x, tid = threadIdx.x;

    // ---------------- Phase 1: prep (128 blocks x 128 points) ----------------
    {
        int b = bid >> 4, s = bid & 15;
        __shared__ int sh_cnt, sh_base;
        if (tid == 0) sh_cnt = 0;
        __syncthreads();

        float l1 = 0.f;
        int   m = 0, klocal = -1;
        float cu = 0, cv = 0, cz = 0, pu = 0, pv = 0, pz = 0;
        if (tid < 128) {
            int n  = s * 128 + tid;
            int gi = b * NN + n;
            const float* pp = pred   + gi * 3;
            const float* tt = target + gi * 3;
            const float* xx = points + gi * 3;
            float p0 = pp[0], p1 = pp[1], p2 = pp[2];
            float t0 = tt[0], t1 = tt[1], t2 = tt[2];
            float x0 = xx[0], x1 = xx[1], x2 = xx[2];
            m = mask[gi];

            const unsigned bigbits = __float_as_uint(BIGF);
            g_minbits[0][b][n] = bigbits;
            g_minbits[1][b][n] = bigbits;

            float c0 = x0 + t0, c1 = x1 + t1, c2 = x2 + t2;   // clean
            float q0 = x0 + p0, q1 = x1 + p1, q2 = x2 + p2;   // predp
            cu = c0 + c1; cv = c0 - c1; cz = c2;
            pu = q0 + q1; pv = q0 - q1; pz = q2;

            if (m) {
                l1 = fabsf(p0 - t0) + fabsf(p1 - t1) + fabsf(p2 - t2);
                klocal = atomicAdd(&sh_cnt, 1);
            }
        }
        __syncthreads();
        if (tid == 0) sh_base = atomicAdd(&g_cnt[b], sh_cnt);

        // l1 block reduction
        __shared__ float wsum[8];
#pragma unroll
        for (int o = 16; o > 0; o >>= 1) l1 += __shfl_down_sync(0xffffffffu, l1, o);
        if ((tid & 31) == 0) wsum[tid >> 5] = l1;
        __syncthreads();
        if (tid == 0) {
            float v = 0.f;
#pragma unroll
            for (int i = 0; i < 8; ++i) v += wsum[i];
            g_l1part[bid] = v;
        }
        if (m) {
            int k = sh_base + klocal;
            g_valid[0][b][k] = make_float4(cu, cv, cz, 0.f);
            g_valid[1][b][k] = make_float4(pu, pv, pz, 0.f);
        }
    }

    grid_barrier();

    // ---------------- Phase 2: chamfer (128 jobs == 128 blocks) ----------------
    {
        int rhalf = bid & 1;
        int qc    = (bid >> 1) & 3;
        int task  = bid >> 3;            // 0..15
        int b     = task >> 1;
        int dir   = task & 1;            // 0: clean->pred, 1: pred->clean
        int cnt   = g_cnt[b];

        int qn = (cnt + 3) >> 2, q_lo = qc * qn,   q_hi = min(q_lo + qn, cnt);
        int rn = (cnt + 1) >> 1, r_lo = rhalf * rn, r_hi = min(r_lo + rn, cnt);

        const float4* __restrict__ Q = g_valid[dir][b];
        const float4* __restrict__ R = g_valid[dir ^ 1][b];

        __shared__ float4 tile[RTILE];
        int  qi1 = q_lo + tid;
        int  qi2 = q_lo + tid + TB;
        bool v1  = qi1 < q_hi;
        bool v2  = qi2 < q_hi;
        float4 a = v1 ? Q[qi1] : make_float4(0.f, 0.f, 0.f, 0.f);
        float4 c = v2 ? Q[qi2] : make_float4(0.f, 0.f, 0.f, 0.f);
        float mn1 = BIGF, mn2 = BIGF;

        for (int r0 = r_lo; r0 < r_hi; r0 += RTILE) {
            int r = r0 + tid;
            tile[tid] = (r < r_hi) ? R[r] : make_float4(BIGF, BIGF, BIGF, 0.f);
            __syncthreads();
            if (v2) {
#pragma unroll 8
                for (int j = 0; j < RTILE; ++j) {
                    float4 y = tile[j];
                    float d1 = a.x - y.x, d2 = a.y - y.y, d3 = a.z - y.z;
                    float d  = fmaxf(fabsf(d1), fabsf(d2)) + fabsf(d3);
                    mn1 = fminf(mn1, d);
                    float e1 = c.x - y.x, e2 = c.y - y.y, e3 = c.z - y.z;
                    float e  = fmaxf(fabsf(e1), fabsf(e2)) + fabsf(e3);
                    mn2 = fminf(mn2, e);
                }
            } else if (v1) {
#pragma unroll 8
                for (int j = 0; j < RTILE; ++j) {
                    float4 y = tile[j];
                    float d1 = a.x - y.x, d2 = a.y - y.y, d3 = a.z - y.z;
                    float d  = fmaxf(fabsf(d1), fabsf(d2)) + fabsf(d3);
                    mn1 = fminf(mn1, d);
                }
            }
            __syncthreads();
        }
        if (v1) atomicMin(&g_minbits[dir][b][qi1], __float_as_uint(mn1));
        if (v2) atomicMin(&g_minbits[dir][b][qi2], __float_as_uint(mn2));
    }

    // ---------------- Final barrier: arrive-only, block 0 finalizes ----------------
    __threadfence();
    __syncthreads();
    if (bid != 0) {
        if (tid == 0) atomicAdd((unsigned int*)&g_fin, 1u);
        return;
    }
    if (tid == 0) { while (g_fin < GRID - 1) __nanosleep(64); }
    __syncthreads();
    __threadfence();

    // ---------------- Phase 3: finalize (block 0) ----------------
    {
        float acc = 0.f;                         // sum_b (S1[b]+S2[b]) / cnt[b]
        for (int b = 0; b < BB; ++b) {
            int cnt = g_cnt[b];
            float inv = 1.f / (float)cnt;
            float s = 0.f;
            for (int k = tid; k < cnt; k += TB)
                s += __uint_as_float(g_minbits[0][b][k])
                   + __uint_as_float(g_minbits[1][b][k]);
            acc += s * inv;
        }
        float l1p = (tid < GRID) ? g_l1part[tid] : 0.f;  // GRID==128 < TB

        __shared__ float wa[8], wl[8];
#pragma unroll
        for (int o = 16; o > 0; o >>= 1) {
            acc += __shfl_down_sync(0xffffffffu, acc, o);
            l1p += __shfl_down_sync(0xffffffffu, l1p, o);
        }
        if ((tid & 31) == 0) { wa[tid >> 5] = acc; wl[tid >> 5] = l1p; }
        __syncthreads();
        if (tid == 0) {
            float cdsum = 0.f, l1num = 0.f;
#pragma unroll
            for (int i = 0; i < 8; ++i) { cdsum += wa[i]; l1num += wl[i]; }
            int msum = 0;
#pragma unroll
            for (int b = 0; b < BB; ++b) msum += g_cnt[b];
            float l1 = l1num / 3.0f / (float)msum;
            float cd = cdsum / (float)BB;
            out[0] = l1 + expf(-l1) * cd;
        }
        __syncthreads();
        // reset state for next graph replay (deterministic self-cleaning)
        if (tid < BB) g_cnt[tid] = 0;
        if (tid == 0) g_fin = 0;
    }
}

extern "C" void kernel_launch(void* const* d_in, const int* in_sizes, int n_in,
                              void* d_out, int out_size) {
    const float* pred   = (const float*)d_in[0];
    const float* target = (const float*)d_in[1];
    const int*   mask   = (const int*)  d_in[2];
    const float* points = (const float*)d_in[3];
    float* out = (float*)d_out;

    fused_kernel<<<GRID, TB>>>(pred, target, mask, points, out);
}

// round 4
// speedup vs baseline: 1.4161x; 1.4161x over previous
#include <cuda_runtime.h>
#include <cuda_bf16.h>

#define BB 8
#define NN 2048
#define BIGF 1e30f

// chamfer tiling
#define TB     128
#define QPT    2
#define QCHUNK (QPT * TB)     // 256 queries per block
#define RTILE  64             // refs per block
#define GX     (NN / QCHUNK)  // 8
#define GY     (NN / RTILE)   // 32
#define GZ     (2 * BB)       // 16
#define NBLK   (GX * GY * GZ) // 4096

// Scratch (allocation-free). Points stored transformed: (x+y, x-y, z, 0)
// g_valid[0] = clean (points+target), g_valid[1] = predp (points+pred)
__device__ float4       g_valid[2][BB][NN];
__device__ unsigned int g_minbits[2][BB][NN];
__device__ int          g_cnt[BB];        // zero at load; reset by last block each call
__device__ float        g_l1part[128];
__device__ unsigned int g_done;           // zero at load; reset by last block each call

// ---------------------------------------------------------------------------
// Kernel 1: prep — 128 blocks x 128 threads, one point per thread.
// ---------------------------------------------------------------------------
__global__ void __launch_bounds__(128)
prep_kernel(const float* __restrict__ pred,
            const float* __restrict__ target,
            const int*   __restrict__ mask,
            const float* __restrict__ points) {
    int bid = blockIdx.x, tid = threadIdx.x;
    int b = bid >> 4, s = bid & 15;
    int n  = s * 128 + tid;
    int gi = b * NN + n;

    const float* pp = pred   + gi * 3;
    const float* tt = target + gi * 3;
    const float* xx = points + gi * 3;
    float p0 = pp[0], p1 = pp[1], p2 = pp[2];
    float t0 = tt[0], t1 = tt[1], t2 = tt[2];
    float x0 = xx[0], x1 = xx[1], x2 = xx[2];
    int m = mask[gi];

    const unsigned bigbits = __float_as_uint(BIGF);
    g_minbits[0][b][n] = bigbits;
    g_minbits[1][b][n] = bigbits;

    float c0 = x0 + t0, c1 = x1 + t1, c2 = x2 + t2;   // clean
    float q0 = x0 + p0, q1 = x1 + p1, q2 = x2 + p2;   // predp
    float l1 = 0.f;

    __shared__ int sh_cnt, sh_base;
    if (tid == 0) sh_cnt = 0;
    __syncthreads();
    int klocal = -1;
    if (m) {
        l1 = fabsf(p0 - t0) + fabsf(p1 - t1) + fabsf(p2 - t2);
        klocal = atomicAdd(&sh_cnt, 1);
    }
    __syncthreads();
    if (tid == 0) sh_base = atomicAdd(&g_cnt[b], sh_cnt);

    // l1 block reduction (4 warps)
    __shared__ float wsum[4];
#pragma unroll
    for (int o = 16; o > 0; o >>= 1) l1 += __shfl_down_sync(0xffffffffu, l1, o);
    if ((tid & 31) == 0) wsum[tid >> 5] = l1;
    __syncthreads();
    if (tid == 0)
        g_l1part[bid] = wsum[0] + wsum[1] + wsum[2] + wsum[3];

    if (m) {
        int k = sh_base + klocal;
        g_valid[0][b][k] = make_float4(c0 + c1, c0 - c1, c2, 0.f);
        g_valid[1][b][k] = make_float4(q0 + q1, q0 - q1, q2, 0.f);
    }
}

// ---------------------------------------------------------------------------
// Kernel 2: chamfer (4096 blocks) + last-block finalize.
// |dx|+|dy|+|dz| == max(|du|,|dv|) + |dz| with (u,v) = (x+y, x-y).
// ---------------------------------------------------------------------------
__global__ void __launch_bounds__(TB)
chamfer_kernel(float* __restrict__ out) {
    int tid  = threadIdx.x;
    int task = blockIdx.z;
    int b    = task >> 1;
    int dir  = task & 1;              // 0: clean->pred, 1: pred->clean
    int cnt  = g_cnt[b];

    int q_base = blockIdx.x * QCHUNK;
    int r_base = blockIdx.y * RTILE;

    if (q_base < cnt && r_base < cnt) {
        const float4* __restrict__ Q = g_valid[dir][b];
        const float4* __restrict__ R = g_valid[dir ^ 1][b];

        __shared__ float4 tile[RTILE];
        if (tid < RTILE) {
            int r = r_base + tid;
            tile[tid] = (r < cnt) ? R[r] : make_float4(BIGF, BIGF, BIGF, 0.f);
        }

        int  qi1 = q_base + tid;
        int  qi2 = q_base + tid + TB;
        bool v1  = qi1 < cnt;
        bool v2  = qi2 < cnt;
        float4 a = Q[qi1];            // always < NN; garbage beyond cnt unused
        float4 c = Q[qi2 < NN ? qi2 : 0];
        float mn1 = BIGF, mn2 = BIGF;
        __syncthreads();

#pragma unroll 8
        for (int j = 0; j < RTILE; ++j) {
            float4 y = tile[j];                       // uniform LDS.128 broadcast
            float d1 = a.x - y.x, d2 = a.y - y.y, d3 = a.z - y.z;
            float d  = fmaxf(fabsf(d1), fabsf(d2)) + fabsf(d3);
            mn1 = fminf(mn1, d);
            float e1 = c.x - y.x, e2 = c.y - y.y, e3 = c.z - y.z;
            float e  = fmaxf(fabsf(e1), fabsf(e2)) + fabsf(e3);
            mn2 = fminf(mn2, e);
        }
        if (v1) atomicMin(&g_minbits[dir][b][qi1], __float_as_uint(mn1));
        if (v2) atomicMin(&g_minbits[dir][b][qi2], __float_as_uint(mn2));
    }

    // -------- arrive; last block finalizes --------
    __threadfence();
    __syncthreads();
    __shared__ int is_last;
    if (tid == 0)
        is_last = (atomicAdd(&g_done, 1u) == NBLK - 1);
    __syncthreads();
    if (!is_last) return;

    float acc = 0.f;                         // sum_b (S1[b]+S2[b]) / cnt[b]
    for (int bb = 0; bb < BB; ++bb) {
        int c2 = g_cnt[bb];
        float inv = 1.f / (float)c2;
        float s = 0.f;
        for (int k = tid; k < c2; k += TB)
            s += __uint_as_float(g_minbits[0][bb][k])
               + __uint_as_float(g_minbits[1][bb][k]);
        acc += s * inv;
    }
    float l1p = g_l1part[tid];               // 128 partials, TB==128

    __shared__ float wa[4], wl[4];
#pragma unroll
    for (int o = 16; o > 0; o >>= 1) {
        acc += __shfl_down_sync(0xffffffffu, acc, o);
        l1p += __shfl_down_sync(0xffffffffu, l1p, o);
    }
    if ((tid & 31) == 0) { wa[tid >> 5] = acc; wl[tid >> 5] = l1p; }
    __syncthreads();
    if (tid == 0) {
        float cdsum = wa[0] + wa[1] + wa[2] + wa[3];
        float l1num = wl[0] + wl[1] + wl[2] + wl[3];
        int msum = 0;
#pragma unroll
        for (int bb = 0; bb < BB; ++bb) msum += g_cnt[bb];
        float l1 = l1num / 3.0f / (float)msum;
        float cd = cdsum / (float)BB;
        out[0] = l1 + expf(-l1) * cd;
        // reset state for next graph replay
        g_done = 0;
    }
    if (tid < BB) g_cnt[tid] = 0;
}

// ---------------------------------------------------------------------------
extern "C" void kernel_launch(void* const* d_in, const int* in_sizes, int n_in,
                              void* d_out, int out_size) {
    const float* pred   = (const float*)d_in[0];
    const float* target = (const float*)d_in[1];
    const int*   mask   = (const int*)  d_in[2];
    const float* points = (const float*)d_in[3];
    float* out = (float*)d_out;

    prep_kernel<<<128, 128>>>(pred, target, mask, points);

    dim3 grid(GX, GY, GZ);   // (8, 32, 16)
    chamfer_kernel<<<grid, TB>>>(out);
}

// round 5
// speedup vs baseline: 1.5381x; 1.0862x over previous
#include <cuda_runtime.h>
#include <cuda_bf16.h>

#define BB 8
#define NN 2048
#define BIGF 1e30f

// chamfer shape
#define TB     128
#define QPT    4
#define QCHUNK (QPT * TB)       // 512 fixed queries per q-chunk
#define GQ     (NN / QCHUNK)    // 4  (covers cnt up to 2048)
#define RSPLIT 32               // cnt-relative ref chunks
#define RTILE  64               // max rn = ceil(2048/32)
#define GZ     (2 * BB)         // 16 tasks
#define ARR_PER_TASK (GQ * RSPLIT)  // 128 arrivals per task

// Scratch (allocation-free). Points stored transformed: (x+y, x-y, z, 0)
// g_valid[0] = clean (points+target), g_valid[1] = predp (points+pred)
__device__ __align__(16) float4       g_valid[2][BB][NN];
__device__ __align__(16) unsigned int g_minbits[2][BB][NN];
__device__ int          g_cnt[BB];          // zero at load; reset by last block
__device__ float        g_l1part[128];
__device__ unsigned int g_done_task[GZ];    // hierarchical arrive, level 1
__device__ unsigned int g_done;             // level 2

// ---------------------------------------------------------------------------
// Kernel 1: prep — 128 blocks x 128 threads, one point per thread.
// ---------------------------------------------------------------------------
__global__ void __launch_bounds__(128)
prep_kernel(const float* __restrict__ pred,
            const float* __restrict__ target,
            const int*   __restrict__ mask,
            const float* __restrict__ points) {
    int bid = blockIdx.x, tid = threadIdx.x;
    int b = bid >> 4, s = bid & 15;
    int n  = s * 128 + tid;
    int gi = b * NN + n;

    const float* pp = pred   + gi * 3;
    const float* tt = target + gi * 3;
    const float* xx = points + gi * 3;
    float p0 = pp[0], p1 = pp[1], p2 = pp[2];
    float t0 = tt[0], t1 = tt[1], t2 = tt[2];
    float x0 = xx[0], x1 = xx[1], x2 = xx[2];
    int m = mask[gi];

    const unsigned bigbits = __float_as_uint(BIGF);
    g_minbits[0][b][n] = bigbits;
    g_minbits[1][b][n] = bigbits;

    float c0 = x0 + t0, c1 = x1 + t1, c2 = x2 + t2;   // clean
    float q0 = x0 + p0, q1 = x1 + p1, q2 = x2 + p2;   // predp
    float l1 = 0.f;

    __shared__ int sh_cnt, sh_base;
    if (tid == 0) sh_cnt = 0;
    __syncthreads();
    int klocal = -1;
    if (m) {
        l1 = fabsf(p0 - t0) + fabsf(p1 - t1) + fabsf(p2 - t2);
        klocal = atomicAdd(&sh_cnt, 1);
    }
    __syncthreads();
    if (tid == 0) sh_base = atomicAdd(&g_cnt[b], sh_cnt);

    __shared__ float wsum[4];
#pragma unroll
    for (int o = 16; o > 0; o >>= 1) l1 += __shfl_down_sync(0xffffffffu, l1, o);
    if ((tid & 31) == 0) wsum[tid >> 5] = l1;
    __syncthreads();
    if (tid == 0)
        g_l1part[bid] = wsum[0] + wsum[1] + wsum[2] + wsum[3];

    if (m) {
        int k = sh_base + klocal;
        g_valid[0][b][k] = make_float4(c0 + c1, c0 - c1, c2, 0.f);
        g_valid[1][b][k] = make_float4(q0 + q1, q0 - q1, q2, 0.f);
    }
}

// ---------------------------------------------------------------------------
// Inner loop, specialized per number of active query slots (block-uniform).
// |dx|+|dy|+|dz| == max(|du|,|dv|) + |dz| with (u,v) = (x+y, x-y).
// ---------------------------------------------------------------------------
template<int NU>
__device__ __forceinline__ void inner_loop(const float4* __restrict__ tile, int rlen,
                                           const float* qx, const float* qy,
                                           const float* qz, float* mn) {
#pragma unroll 8
    for (int j = 0; j < rlen; ++j) {
        float4 y = tile[j];                       // uniform LDS.128 broadcast
#pragma unroll
        for (int u = 0; u < NU; ++u) {
            float d = fmaxf(fabsf(qx[u] - y.x), fabsf(qy[u] - y.y)) + fabsf(qz[u] - y.z);
            mn[u] = fminf(mn[u], d);
        }
    }
}

// ---------------------------------------------------------------------------
// Kernel 2: chamfer, grid (GQ, RSPLIT, GZ) = (4, 32, 16) = 2048 blocks.
// r-chunks are cnt-relative (no dead r blocks); last block finalizes.
// ---------------------------------------------------------------------------
__global__ void __launch_bounds__(TB)
chamfer_kernel(float* __restrict__ out) {
    int tid  = threadIdx.x;
    int task = blockIdx.z;
    int b    = task >> 1;
    int dir  = task & 1;              // 0: clean->pred, 1: pred->clean
    int cnt  = g_cnt[b];

    __shared__ float4 tile[RTILE];
    int q_lo = blockIdx.x * QCHUNK;

    if (q_lo < cnt) {
        int q_hi = min(q_lo + QCHUNK, cnt);
        int nu   = (q_hi - q_lo + TB - 1) >> 7;            // 1..4, block-uniform
        int rn   = (cnt + RSPLIT - 1) / RSPLIT;            // <= 64
        int r_lo = blockIdx.y * rn;
        int rlen = min(rn, cnt - r_lo);

        if (rlen > 0) {
            const float4* __restrict__ Q = g_valid[dir][b];
            const float4* __restrict__ R = g_valid[dir ^ 1][b];

            if (tid < RTILE)
                tile[tid] = (tid < rlen) ? R[r_lo + tid]
                                         : make_float4(BIGF, BIGF, BIGF, 0.f);

            float qx[QPT], qy[QPT], qz[QPT], mn[QPT];
#pragma unroll
            for (int u = 0; u < QPT; ++u) {
                int qi = q_lo + u * TB + tid;              // always < NN
                float4 v = Q[qi];                          // garbage beyond cnt unused
                qx[u] = v.x; qy[u] = v.y; qz[u] = v.z;
                mn[u] = BIGF;
            }
            __syncthreads();

            switch (nu) {
                case 4: inner_loop<4>(tile, rlen, qx, qy, qz, mn); break;
                case 3: inner_loop<3>(tile, rlen, qx, qy, qz, mn); break;
                case 2: inner_loop<2>(tile, rlen, qx, qy, qz, mn); break;
                default: inner_loop<1>(tile, rlen, qx, qy, qz, mn); break;
            }

#pragma unroll
            for (int u = 0; u < QPT; ++u) {
                int qi = q_lo + u * TB + tid;
                if (qi < q_hi)
                    atomicMin(&g_minbits[dir][b][qi], __float_as_uint(mn[u]));
            }
        }
    }

    // -------- hierarchical arrive; globally-last block finalizes --------
    __threadfence();
    __syncthreads();
    __shared__ int is_last;
    if (tid == 0) {
        is_last = 0;
        if (atomicAdd(&g_done_task[task], 1u) == ARR_PER_TASK - 1) {
            __threadfence();
            is_last = (atomicAdd(&g_done, 1u) == GZ - 1);
        }
    }
    __syncthreads();
    if (!is_last) return;

    // -------- finalize (one block, vectorized) --------
    float acc = 0.f;                         // sum_b (S1[b]+S2[b]) / cnt[b]
    for (int bb = 0; bb < BB; ++bb) {
        int c = g_cnt[bb];
        const uint4* __restrict__ p0 = (const uint4*)g_minbits[0][bb];
        const uint4* __restrict__ p1 = (const uint4*)g_minbits[1][bb];
        int nv = c >> 2;
        float s0 = 0.f, s1 = 0.f;
        for (int k = tid; k < nv; k += TB) {
            uint4 a = p0[k], d = p1[k];
            s0 += (__uint_as_float(a.x) + __uint_as_float(a.y))
                + (__uint_as_float(a.z) + __uint_as_float(a.w));
            s1 += (__uint_as_float(d.x) + __uint_as_float(d.y))
                + (__uint_as_float(d.z) + __uint_as_float(d.w));
        }
        if (tid < (c & 3)) {
            int k = (c & ~3) + tid;
            s0 += __uint_as_float(g_minbits[0][bb][k]);
            s1 += __uint_as_float(g_minbits[1][bb][k]);
        }
        acc += (s0 + s1) / (float)c;
    }
    float l1p = g_l1part[tid];               // 128 partials, TB == 128

    __shared__ float wa[4], wl[4];
#pragma unroll
    for (int o = 16; o > 0; o >>= 1) {
        acc += __shfl_down_sync(0xffffffffu, acc, o);
        l1p += __shfl_down_sync(0xffffffffu, l1p, o);
    }
    if ((tid & 31) == 0) { wa[tid >> 5] = acc; wl[tid >> 5] = l1p; }
    __syncthreads();
    if (tid == 0) {
        float cdsum = wa[0] + wa[1] + wa[2] + wa[3];
        float l1num = wl[0] + wl[1] + wl[2] + wl[3];
        int msum = 0;
#pragma unroll
        for (int bb = 0; bb < BB; ++bb) msum += g_cnt[bb];
        float l1 = l1num / 3.0f / (float)msum;
        float cd = cdsum / (float)BB;
        out[0] = l1 + expf(-l1) * cd;
        g_done = 0;                          // reset for next graph replay
    }
    if (tid < BB)  g_cnt[tid] = 0;
    if (tid < GZ)  g_done_task[tid] = 0;
}

// ---------------------------------------------------------------------------
extern "C" void kernel_launch(void* const* d_in, const int* in_sizes, int n_in,
                              void* d_out, int out_size) {
    const float* pred   = (const float*)d_in[0];
    const float* target = (const float*)d_in[1];
    const int*   mask   = (const int*)  d_in[2];
    const float* points = (const float*)d_in[3];
    float* out = (float*)d_out;

    prep_kernel<<<128, 128>>>(pred, target, mask, points);

    dim3 grid(GQ, RSPLIT, GZ);   // (4, 32, 16)
    chamfer_kernel<<<grid, TB>>>(out);
}